// round 13
// baseline (speedup 1.0000x reference)
#include <cuda_runtime.h>
#include <cuda_bf16.h>
#include <cuda_fp16.h>
#include <cstdint>

#define N_NODES 20000
#define F_DIM   512
#define H_DIM   128
#define C_DIM   64
#define N_EDGES 640000
#define PAD_ROWS 20096       // 157 * 128
#define RP_STRIDE 20004      // N_NODES+1 padded to 4-int alignment

// ---------------------------------------------------------------------------
// Scratch (static device globals; no runtime allocation allowed)
// ---------------------------------------------------------------------------
__device__ __half g_emb1h[9 * N_NODES * H_DIM];   // fp16 tables (combo); self = combo gc*3
__device__ __half g_emb2h[9 * N_NODES * C_DIM];

// fp16 GEMM operands (single-pass fp16 mma)
__device__ __half g_xh[3 * PAD_ROWS * F_DIM];     // [view][row][k]
__device__ __half g_wt[9 * H_DIM * F_DIM];        // [combo][n][k]
__device__ __half g_hh[3 * PAD_ROWS * H_DIM];     // [gc][row][k]
__device__ __half g_wt2[9 * C_DIM * H_DIM];       // [combo][n][k]

// CSR scratch
__device__ int  g_rowptr[3 * RP_STRIDE];
__device__ int  g_cursor[3 * N_NODES];
__device__ int2 g_edge[3 * N_EDGES];              // {col, w-as-int}

// combo -> which x / adjacency feeds it. combo = gc*3 + role.
__constant__ int c_perm[9] = {0,1,2, 1,0,2, 2,0,1};

// ---------------------------------------------------------------------------
// PTX helpers (base-target only: sm_80+ features)
// ---------------------------------------------------------------------------
__device__ __forceinline__ uint32_t smem_u32(const void* p) {
    uint32_t a;
    asm("{ .reg .u64 t; cvta.to.shared.u64 t, %1; cvt.u32.u64 %0, t; }"
        : "=r"(a) : "l"(p));
    return a;
}

__device__ __forceinline__ void cp_async16(uint32_t dst, const void* src) {
    asm volatile("cp.async.cg.shared.global [%0], [%1], 16;"
                 :: "r"(dst), "l"(src) : "memory");
}
#define CP_COMMIT() asm volatile("cp.async.commit_group;" ::: "memory")
#define CP_WAIT(n)  asm volatile("cp.async.wait_group %0;" :: "n"(n) : "memory")

__device__ __forceinline__ void ldsm_x4(uint32_t& r0, uint32_t& r1,
                                        uint32_t& r2, uint32_t& r3, uint32_t addr) {
    asm volatile("ldmatrix.sync.aligned.m8n8.x4.shared.b16 {%0,%1,%2,%3}, [%4];"
                 : "=r"(r0), "=r"(r1), "=r"(r2), "=r"(r3) : "r"(addr));
}

__device__ __forceinline__ void mma_f16(float* d, const uint32_t* a,
                                        const uint32_t* b) {
    asm volatile(
        "mma.sync.aligned.m16n8k16.row.col.f32.f16.f16.f32 "
        "{%0,%1,%2,%3}, {%4,%5,%6,%7}, {%8,%9}, {%0,%1,%2,%3};"
        : "+f"(d[0]), "+f"(d[1]), "+f"(d[2]), "+f"(d[3])
        : "r"(a[0]), "r"(a[1]), "r"(a[2]), "r"(a[3]), "r"(b[0]), "r"(b[1]));
}

__device__ __forceinline__ uint32_t h2u(__half2 h) {
    return *(uint32_t*)&h;
}

// ---------------------------------------------------------------------------
// K0: csr_zero — own kernel: all cursor zeroes visible before hist atomics.
// ---------------------------------------------------------------------------
__global__ void csr_zero_kernel() {
    int i = blockIdx.x * blockDim.x + threadIdx.x;
    if (i < 3 * N_NODES) g_cursor[i] = 0;
}

// ---------------------------------------------------------------------------
// K1: fused prep — cvt_x (x2 ILP) | cvt_w | cvt_w2 | csr_hist
// ---------------------------------------------------------------------------
#define NB_SPLITX 15000                  // 2 float4 per thread (strided)
#define SPLITX_STRIDE (NB_SPLITX * 256)
#define NB_SPLITW 2304
#define NB_SPLITW2 288
#define NB_HIST_PER 625
#define B_SPLITW  (NB_SPLITX)
#define B_SPLITW2 (B_SPLITW + NB_SPLITW)
#define B_HIST    (B_SPLITW2 + NB_SPLITW2)
#define NB_PREP   (B_HIST + 3 * NB_HIST_PER)

__global__ void __launch_bounds__(256)
prep_kernel(const float* __restrict__ x1, const float* __restrict__ x2,
            const float* __restrict__ x3, const float* __restrict__ W1,
            const float* __restrict__ W2,
            const int* __restrict__ s0, const int* __restrict__ s1,
            const int* __restrict__ s2) {
    const int bid = blockIdx.x;
    const int tid = threadIdx.x;

    if (bid < NB_SPLITX) {
#pragma unroll
        for (int r = 0; r < 2; r++) {
            int i = bid * 256 + tid + r * SPLITX_STRIDE;  // one float4
            const int per_view = N_NODES * (F_DIM / 4);
            const int view = i / per_view;
            const int rem  = i - view * per_view;
            const int row  = rem / (F_DIM / 4);
            const int kg   = rem - row * (F_DIM / 4);
            const float* X = (view == 0) ? x1 : (view == 1) ? x2 : x3;
            float4 f = ((const float4*)X)[rem];
            __half2 a = __float22half2_rn(make_float2(f.x, f.y));
            __half2 b = __float22half2_rn(make_float2(f.z, f.w));
            size_t off = ((size_t)view * PAD_ROWS + row) * F_DIM + kg * 4;
            *(uint2*)&g_xh[off] = make_uint2(h2u(a), h2u(b));
        }
    } else if (bid < B_SPLITW2) {
        int i = (bid - B_SPLITW) * 256 + tid;   // over 9*512*128, n fastest
        const int b = i / (F_DIM * H_DIM);
        const int rem = i - b * (F_DIM * H_DIM);
        const int k = rem / H_DIM;
        const int n = rem - k * H_DIM;
        g_wt[((size_t)b * H_DIM + n) * F_DIM + k] = __float2half_rn(W1[i]);
    } else if (bid < B_HIST) {
        int i = (bid - B_SPLITW2) * 256 + tid;  // over 9*128*64
        const int b = i / (H_DIM * C_DIM);
        const int rem = i - b * (H_DIM * C_DIM);
        const int k = rem / C_DIM;
        const int n = rem - k * C_DIM;
        g_wt2[((size_t)b * C_DIM + n) * H_DIM + k] = __float2half_rn(W2[i]);
    } else {
        const int rel = bid - B_HIST;
        const int a = rel / NB_HIST_PER;
        const int blk = rel - a * NB_HIST_PER;
        const int* __restrict__ s = (a == 0) ? s0 : (a == 1) ? s1 : s2;
        int* __restrict__ cur = g_cursor + a * N_NODES;
        const int base = blk * 1024 + tid;
#pragma unroll
        for (int k = 0; k < 4; k++)
            atomicAdd(&cur[__ldg(&s[base + k * 256])], 1);
    }
}

// ---------------------------------------------------------------------------
// K2: csr_scan — own kernel (3 blocks, 256 threads).
// ---------------------------------------------------------------------------
__global__ void __launch_bounds__(256) csr_scan_kernel() {
    const int a = blockIdx.x;
    __shared__ int s_warp[9];
    int* cnt = g_cursor + a * N_NODES;
    int* rp  = g_rowptr + a * RP_STRIDE;
    const int tid = threadIdx.x;
    const int lane = tid & 31;
    const int w = tid >> 5;
    int carry = 0;
    for (int base = 0; base < N_NODES; base += 1024) {
        const int idx = base + tid * 4;
        int v0 = 0, v1 = 0, v2 = 0, v3 = 0;
        if (idx + 3 < N_NODES) {
            int4 t = *(const int4*)&cnt[idx];
            v0 = t.x; v1 = t.y; v2 = t.z; v3 = t.w;
        } else {
            if (idx + 0 < N_NODES) v0 = cnt[idx + 0];
            if (idx + 1 < N_NODES) v1 = cnt[idx + 1];
            if (idx + 2 < N_NODES) v2 = cnt[idx + 2];
            if (idx + 3 < N_NODES) v3 = cnt[idx + 3];
        }
        const int tsum = v0 + v1 + v2 + v3;
        int sc = tsum;
#pragma unroll
        for (int o = 1; o < 32; o <<= 1) {
            int n = __shfl_up_sync(0xffffffff, sc, o);
            if (lane >= o) sc += n;
        }
        if (lane == 31) s_warp[w] = sc;
        __syncthreads();
        if (w == 0) {
            int x = (lane < 8) ? s_warp[lane] : 0;
#pragma unroll
            for (int o = 1; o < 8; o <<= 1) {
                int n = __shfl_up_sync(0xffffffff, x, o);
                if (lane >= o) x += n;
            }
            if (lane < 8) s_warp[lane] = x;
            if (lane == 7) s_warp[8] = x;
        }
        __syncthreads();
        const int warp_off = (w == 0) ? 0 : s_warp[w - 1];
        const int excl = carry + warp_off + (sc - tsum);
        const int p0 = excl, p1 = p0 + v0, p2 = p1 + v1, p3 = p2 + v2;
        if (idx + 3 < N_NODES) {
            *(int4*)&rp[idx]  = make_int4(p0, p1, p2, p3);
            *(int4*)&cnt[idx] = make_int4(p0, p1, p2, p3);
        } else {
            if (idx + 0 < N_NODES) { rp[idx + 0] = p0; cnt[idx + 0] = p0; }
            if (idx + 1 < N_NODES) { rp[idx + 1] = p1; cnt[idx + 1] = p1; }
            if (idx + 2 < N_NODES) { rp[idx + 2] = p2; cnt[idx + 2] = p2; }
            if (idx + 3 < N_NODES) { rp[idx + 3] = p3; cnt[idx + 3] = p3; }
        }
        carry += s_warp[8];
        __syncthreads();
    }
    if (tid == 0) rp[N_NODES] = carry;
}

// ---------------------------------------------------------------------------
// K3: GEMM1 (mma.sync fp16) with csr_fill piggybacked at the END of the grid.
// Single __syncthreads per K-iteration: wait -> sync -> prefetch -> compute.
// (The sync proves all warps finished iter it-1, i.e. done reading buffer
// (it+2)%3 before this iteration's prefetch overwrites it.)
// ---------------------------------------------------------------------------
#define TILE_BYTES 16384                  // 128 rows x 128B
#define STAGE_BYTES (2 * TILE_BYTES)      // A + B
#define GSM_TOTAL (3 * STAGE_BYTES)       // 3 stages = 96KB
#define NB_GEMM1 (157 * 9)
#define NB_FILL (3 * NB_HIST_PER)

__global__ void __launch_bounds__(256, 2)
gemm1_mma_kernel(const int* __restrict__ s0, const int* __restrict__ s1,
                 const int* __restrict__ s2, const int* __restrict__ d0,
                 const int* __restrict__ d1, const int* __restrict__ d2,
                 const float* __restrict__ v0, const float* __restrict__ v1,
                 const float* __restrict__ v2) {
    if (blockIdx.x >= NB_GEMM1) {         // piggybacked fill blocks (grid tail)
        const int rel = blockIdx.x - NB_GEMM1;
        const int a = rel / NB_HIST_PER;
        const int blk = rel - a * NB_HIST_PER;
        const int*   __restrict__ s = (a == 0) ? s0 : (a == 1) ? s1 : s2;
        const int*   __restrict__ d = (a == 0) ? d0 : (a == 1) ? d1 : d2;
        const float* __restrict__ v = (a == 0) ? v0 : (a == 1) ? v1 : v2;
        int* __restrict__ cur = g_cursor + a * N_NODES;
        int2* __restrict__ eo = g_edge + (size_t)a * N_EDGES;
        const int base = blk * 1024 + threadIdx.x;
#pragma unroll
        for (int k = 0; k < 4; k++) {
            const int e = base + k * 256;
            const int ss = __ldg(&s[e]);
            const int dd = __ldg(&d[e]);
            const float vv = __ldg(&v[e]);
            int pos = atomicAdd(&cur[ss], 1);
            eo[pos] = make_int2(dd, __float_as_int(vv));
        }
        return;
    }
    extern __shared__ char smem[];
    const uint32_t sb = smem_u32(smem);
    const int tid = threadIdx.x;
    const int wid = tid >> 5;
    const int lane = tid & 31;
    const int gbid = blockIdx.x;
    const int tile = gbid % 157;
    const int b = gbid / 157;
    const int view = c_perm[b];
    const int rowBase = tile * 128;

    const int wm = wid >> 1;
    const int wn = wid & 1;

    const int arow_l = (lane & 15);
    const uint32_t akh = (uint32_t)(lane >> 4) * 16;
    const int brow_l = (lane & 7) + ((lane >> 4) << 3);
    const uint32_t bkh = (uint32_t)((lane >> 3) & 1) * 16;

    float cfrag[2][8][4];
#pragma unroll
    for (int mi = 0; mi < 2; mi++)
#pragma unroll
        for (int nj = 0; nj < 8; nj++)
#pragma unroll
            for (int q = 0; q < 4; q++) cfrag[mi][nj][q] = 0.f;

    const char* Abase = (const char*)(g_xh +
        ((size_t)view * PAD_ROWS + rowBase) * F_DIM);
    const char* Bbase = (const char*)(g_wt + (size_t)b * H_DIM * F_DIM);

    auto prefetch = [&](int c, int bufi) {
        const char* Asrc = Abase + c * 128;
        const char* Bsrc = Bbase + c * 128;
        const uint32_t Ab = sb + bufi * STAGE_BYTES;
        const uint32_t Bb = Ab + TILE_BYTES;
#pragma unroll
        for (int i = 0; i < 4; i++) {
            int idx = tid + i * 256;
            int row = idx >> 3;
            int ch  = idx & 7;
            uint32_t off = row * 128 + ch * 16;
            uint32_t sw = off ^ ((off >> 3) & 0x70);
            cp_async16(Ab + sw, Asrc + (size_t)row * (F_DIM * 2) + ch * 16);
            cp_async16(Bb + sw, Bsrc + (size_t)row * (F_DIM * 2) + ch * 16);
        }
        CP_COMMIT();
    };

    prefetch(0, 0);
    prefetch(1, 1);

    for (int it = 0; it < 8; it++) {
        const int bufi = it % 3;
        if (it < 7) { CP_WAIT(1); } else { CP_WAIT(0); }
        __syncthreads();
        if (it < 6) prefetch(it + 2, (it + 2) % 3);

        const uint32_t Ab = sb + bufi * STAGE_BYTES;
        const uint32_t Bb = Ab + TILE_BYTES;

#pragma unroll
        for (int k16 = 0; k16 < 4; k16++) {
            const uint32_t kb = k16 * 32;
            uint32_t afrag[2][4];
#pragma unroll
            for (int mi = 0; mi < 2; mi++) {
                const int row = wm * 32 + mi * 16 + arow_l;
                const uint32_t addr =
                    Ab + row * 128 + ((kb + akh) ^ (uint32_t)((row & 7) << 4));
                ldsm_x4(afrag[mi][0], afrag[mi][1], afrag[mi][2], afrag[mi][3], addr);
            }
            uint32_t bfrag[8][2];
#pragma unroll
            for (int bj = 0; bj < 4; bj++) {
                const int row = wn * 64 + bj * 16 + brow_l;
                const uint32_t addr =
                    Bb + row * 128 + ((kb + bkh) ^ (uint32_t)((row & 7) << 4));
                uint32_t r0, r1, r2, r3;
                ldsm_x4(r0, r1, r2, r3, addr);
                bfrag[bj * 2 + 0][0] = r0; bfrag[bj * 2 + 0][1] = r1;
                bfrag[bj * 2 + 1][0] = r2; bfrag[bj * 2 + 1][1] = r3;
            }
#pragma unroll
            for (int mi = 0; mi < 2; mi++)
#pragma unroll
                for (int nj = 0; nj < 8; nj++)
                    mma_f16(cfrag[mi][nj], afrag[mi], bfrag[nj]);
        }
    }

    // Epilogue: half table (self-term read from combo gc*3 in spmm1)
    __half* __restrict__ Couth = g_emb1h + (size_t)b * N_NODES * H_DIM;
    const int mrow0 = rowBase + wm * 32;
    const int ncol0 = wn * 64;
    const int lr = lane >> 2;
    const int lc = (lane & 3) * 2;
#pragma unroll
    for (int mi = 0; mi < 2; mi++) {
#pragma unroll
        for (int nj = 0; nj < 8; nj++) {
            const int r0 = mrow0 + mi * 16 + lr;
            const int cc = ncol0 + nj * 8 + lc;
            if (r0 < N_NODES)
                *(__half2*)&Couth[(size_t)r0 * H_DIM + cc] =
                    __float22half2_rn(make_float2(cfrag[mi][nj][0], cfrag[mi][nj][1]));
            if (r0 + 8 < N_NODES)
                *(__half2*)&Couth[(size_t)(r0 + 8) * H_DIM + cc] =
                    __float22half2_rn(make_float2(cfrag[mi][nj][2], cfrag[mi][nj][3]));
        }
    }
}

// ---------------------------------------------------------------------------
// GEMM2 (mma.sync fp16, single pass): emb2[b] = h[perm[b]] @ W2[b].
// 2 K-iterations, 2-stage cp.async. CTA tile 128x64.
// ---------------------------------------------------------------------------
#define T2_ABYTES 16384                   // 128 rows x 128B
#define T2_BBYTES 8192                    // 64 rows x 128B
#define T2_STAGE  (T2_ABYTES + T2_BBYTES)
#define G2SM_TOTAL (2 * T2_STAGE)         // 48KB

__global__ void __launch_bounds__(256, 2)
gemm2_mma_kernel() {
    extern __shared__ char smem[];
    const uint32_t sb = smem_u32(smem);
    const int tid = threadIdx.x;
    const int wid = tid >> 5;
    const int lane = tid & 31;
    const int tile = blockIdx.x;
    const int b = blockIdx.y;
    const int view = c_perm[b];
    const int rowBase = tile * 128;

    const int wm = wid >> 1;
    const int wn = wid & 1;

    const int arow_l = (lane & 15);
    const uint32_t akh = (uint32_t)(lane >> 4) * 16;
    const int brow_l = (lane & 7) + ((lane >> 4) << 3);
    const uint32_t bkh = (uint32_t)((lane >> 3) & 1) * 16;

    float cfrag[2][4][4];
#pragma unroll
    for (int mi = 0; mi < 2; mi++)
#pragma unroll
        for (int nj = 0; nj < 4; nj++)
#pragma unroll
            for (int q = 0; q < 4; q++) cfrag[mi][nj][q] = 0.f;

    const char* Abase = (const char*)(g_hh +
        ((size_t)view * PAD_ROWS + rowBase) * H_DIM);
    const char* Bbase = (const char*)(g_wt2 + (size_t)b * C_DIM * H_DIM);

    auto prefetch = [&](int c, int bufi) {
        const char* Asrc = Abase + c * 128;
        const char* Bsrc = Bbase + c * 128;
        const uint32_t Ab = sb + bufi * T2_STAGE;
        const uint32_t Bb = Ab + T2_ABYTES;
#pragma unroll
        for (int i = 0; i < 4; i++) {
            int idx = tid + i * 256;
            int row = idx >> 3;
            int ch  = idx & 7;
            uint32_t off = row * 128 + ch * 16;
            uint32_t sw = off ^ ((off >> 3) & 0x70);
            cp_async16(Ab + sw, Asrc + (size_t)row * (H_DIM * 2) + ch * 16);
        }
#pragma unroll
        for (int i = 0; i < 2; i++) {
            int idx = tid + i * 256;
            int row = idx >> 3;
            int ch  = idx & 7;
            uint32_t off = row * 128 + ch * 16;
            uint32_t sw = off ^ ((off >> 3) & 0x70);
            cp_async16(Bb + sw, Bsrc + (size_t)row * (H_DIM * 2) + ch * 16);
        }
        CP_COMMIT();
    };

    prefetch(0, 0);
    prefetch(1, 1);

#pragma unroll
    for (int it = 0; it < 2; it++) {
        if (it == 0) { CP_WAIT(1); } else { CP_WAIT(0); }
        __syncthreads();

        const uint32_t Ab = sb + it * T2_STAGE;
        const uint32_t Bb = Ab + T2_ABYTES;

#pragma unroll
        for (int k16 = 0; k16 < 4; k16++) {
            const uint32_t kb = k16 * 32;
            uint32_t afrag[2][4];
#pragma unroll
            for (int mi = 0; mi < 2; mi++) {
                const int row = wm * 32 + mi * 16 + arow_l;
                const uint32_t addr =
                    Ab + row * 128 + ((kb + akh) ^ (uint32_t)((row & 7) << 4));
                ldsm_x4(afrag[mi][0], afrag[mi][1], afrag[mi][2], afrag[mi][3], addr);
            }
            uint32_t bfrag[4][2];
#pragma unroll
            for (int bj = 0; bj < 2; bj++) {
                const int row = wn * 32 + bj * 16 + brow_l;
                const uint32_t addr =
                    Bb + row * 128 + ((kb + bkh) ^ (uint32_t)((row & 7) << 4));
                uint32_t r0, r1, r2, r3;
                ldsm_x4(r0, r1, r2, r3, addr);
                bfrag[bj * 2 + 0][0] = r0; bfrag[bj * 2 + 0][1] = r1;
                bfrag[bj * 2 + 1][0] = r2; bfrag[bj * 2 + 1][1] = r3;
            }
#pragma unroll
            for (int mi = 0; mi < 2; mi++)
#pragma unroll
                for (int nj = 0; nj < 4; nj++)
                    mma_f16(cfrag[mi][nj], afrag[mi], bfrag[nj]);
        }
        __syncthreads();
    }

    __half* __restrict__ Couth = g_emb2h + (size_t)b * N_NODES * C_DIM;
    const int mrow0 = rowBase + wm * 32;
    const int ncol0 = wn * 32;
    const int lr = lane >> 2;
    const int lc = (lane & 3) * 2;
#pragma unroll
    for (int mi = 0; mi < 2; mi++) {
#pragma unroll
        for (int nj = 0; nj < 4; nj++) {
            const int r0 = mrow0 + mi * 16 + lr;
            const int cc = ncol0 + nj * 8 + lc;
            if (r0 < N_NODES)
                *(__half2*)&Couth[(size_t)r0 * C_DIM + cc] =
                    __float22half2_rn(make_float2(cfrag[mi][nj][0], cfrag[mi][nj][1]));
            if (r0 + 8 < N_NODES)
                *(__half2*)&Couth[(size_t)(r0 + 8) * C_DIM + cc] =
                    __float22half2_rn(make_float2(cfrag[mi][nj][2], cfrag[mi][nj][3]));
        }
    }
}

// ---------------------------------------------------------------------------
// Fused SpMM layer 1: block per node, 64 threads (half2 column pair each).
// Edge loop unrolled x2 for MLP (8 outstanding loads instead of 4).
// ---------------------------------------------------------------------------
__global__ void __launch_bounds__(64) spmm1_kernel(const float* __restrict__ wv1,
                                                   const float* __restrict__ b1) {
    const int i = blockIdx.x;
    const int t = threadIdx.x;
    const int comboOf[3][3] = {{0, 1, 2}, {4, 3, 5}, {7, 8, 6}};

    float2 agg[3] = {{0.f, 0.f}, {0.f, 0.f}, {0.f, 0.f}};

#pragma unroll
    for (int a = 0; a < 3; a++) {
        const int start = g_rowptr[a * RP_STRIDE + i];
        const int end   = g_rowptr[a * RP_STRIDE + i + 1];
        const __half2* __restrict__ T0 =
            (const __half2*)g_emb1h + (size_t)comboOf[0][a] * N_NODES * (H_DIM / 2);
        const __half2* __restrict__ T1 =
            (const __half2*)g_emb1h + (size_t)comboOf[1][a] * N_NODES * (H_DIM / 2);
        const __half2* __restrict__ T2 =
            (const __half2*)g_emb1h + (size_t)comboOf[2][a] * N_NODES * (H_DIM / 2);
        const int2* __restrict__ ew = g_edge + (size_t)a * N_EDGES;

        float2 p0 = {0.f, 0.f}, p1 = {0.f, 0.f}, p2 = {0.f, 0.f};
        int e = start;
        for (; e + 2 <= end; e += 2) {
            const int2 cwa = __ldg(&ew[e]);
            const int2 cwb = __ldg(&ew[e + 1]);
            const float wa = __int_as_float(cwa.y);
            const float wb = __int_as_float(cwb.y);
            const size_t oa = (size_t)cwa.x * (H_DIM / 2) + t;
            const size_t ob = (size_t)cwb.x * (H_DIM / 2) + t;
            float2 a0 = __half22float2(__ldg(&T0[oa]));
            float2 a1 = __half22float2(__ldg(&T1[oa]));
            float2 a2 = __half22float2(__ldg(&T2[oa]));
            float2 b0 = __half22float2(__ldg(&T0[ob]));
            float2 b1v = __half22float2(__ldg(&T1[ob]));
            float2 b2 = __half22float2(__ldg(&T2[ob]));
            p0.x += wa * a0.x + wb * b0.x;  p0.y += wa * a0.y + wb * b0.y;
            p1.x += wa * a1.x + wb * b1v.x; p1.y += wa * a1.y + wb * b1v.y;
            p2.x += wa * a2.x + wb * b2.x;  p2.y += wa * a2.y + wb * b2.y;
        }
        if (e < end) {
            const int2 cw = __ldg(&ew[e]);
            const float w = __int_as_float(cw.y);
            const size_t o = (size_t)cw.x * (H_DIM / 2) + t;
            float2 v0 = __half22float2(__ldg(&T0[o]));
            float2 v1 = __half22float2(__ldg(&T1[o]));
            float2 v2 = __half22float2(__ldg(&T2[o]));
            p0.x += w * v0.x; p0.y += w * v0.y;
            p1.x += w * v1.x; p1.y += w * v1.y;
            p2.x += w * v2.x; p2.y += w * v2.y;
        }
        float w0 = wv1[comboOf[0][a]], w1 = wv1[comboOf[1][a]], w2 = wv1[comboOf[2][a]];
        agg[0].x += w0 * p0.x; agg[0].y += w0 * p0.y;
        agg[1].x += w1 * p1.x; agg[1].y += w1 * p1.y;
        agg[2].x += w2 * p2.x; agg[2].y += w2 * p2.y;
    }

    const size_t NH2 = (size_t)N_NODES * (H_DIM / 2);
    const size_t PH = (size_t)PAD_ROWS * H_DIM;
    const size_t so = (size_t)i * (H_DIM / 2) + t;
#pragma unroll
    for (int gc = 0; gc < 3; gc++) {
        float2 self = __half22float2(
            __ldg((const __half2*)g_emb1h + (size_t)(gc * 3) * NH2 + so));
        float2 bias = *(const float2*)&b1[gc * H_DIM + 2 * t];
        float hx = fmaxf(self.x + 1.01f * agg[gc].x + bias.x, 0.f);
        float hy = fmaxf(self.y + 1.01f * agg[gc].y + bias.y, 0.f);
        const size_t base = (size_t)gc * PH + (size_t)i * H_DIM + 2 * t;
        *(uint32_t*)&g_hh[base] = h2u(__float22half2_rn(make_float2(hx, hy)));
    }
}

// ---------------------------------------------------------------------------
// Fused SpMM layer 2 + final: block per node, 32 threads. Edge loop x2.
// ---------------------------------------------------------------------------
__global__ void __launch_bounds__(32) spmm2_kernel(const float* __restrict__ wv2,
                                                   const float* __restrict__ b2,
                                                   float* __restrict__ out) {
    const int i = blockIdx.x;
    const int t = threadIdx.x;
    const int comboOf[3][3] = {{0, 1, 2}, {4, 3, 5}, {7, 8, 6}};

    float2 agg[3] = {{0.f, 0.f}, {0.f, 0.f}, {0.f, 0.f}};

#pragma unroll
    for (int a = 0; a < 3; a++) {
        const int start = g_rowptr[a * RP_STRIDE + i];
        const int end   = g_rowptr[a * RP_STRIDE + i + 1];
        const __half2* __restrict__ T0 =
            (const __half2*)g_emb2h + (size_t)comboOf[0][a] * N_NODES * (C_DIM / 2);
        const __half2* __restrict__ T1 =
            (const __half2*)g_emb2h + (size_t)comboOf[1][a] * N_NODES * (C_DIM / 2);
        const __half2* __restrict__ T2 =
            (const __half2*)g_emb2h + (size_t)comboOf[2][a] * N_NODES * (C_DIM / 2);
        const int2* __restrict__ ew = g_edge + (size_t)a * N_EDGES;

        float2 p0 = {0.f, 0.f}, p1 = {0.f, 0.f}, p2 = {0.f, 0.f};
        int e = start;
        for (; e + 2 <= end; e += 2) {
            const int2 cwa = __ldg(&ew[e]);
            const int2 cwb = __ldg(&ew[e + 1]);
            const float wa = __int_as_float(cwa.y);
            const float wb = __int_as_float(cwb.y);
            const size_t oa = (size_t)cwa.x * (C_DIM / 2) + t;
            const size_t ob = (size_t)cwb.x * (C_DIM / 2) + t;
            float2 a0 = __half22float2(__ldg(&T0[oa]));
            float2 a1 = __half22float2(__ldg(&T1[oa]));
            float2 a2 = __half22float2(__ldg(&T2[oa]));
            float2 b0 = __half22float2(__ldg(&T0[ob]));
            float2 b1v = __half22float2(__ldg(&T1[ob]));
            float2 b2 = __half22float2(__ldg(&T2[ob]));
            p0.x += wa * a0.x + wb * b0.x;  p0.y += wa * a0.y + wb * b0.y;
            p1.x += wa * a1.x + wb * b1v.x; p1.y += wa * a1.y + wb * b1v.y;
            p2.x += wa * a2.x + wb * b2.x;  p2.y += wa * a2.y + wb * b2.y;
        }
        if (e < end) {
            const int2 cw = __ldg(&ew[e]);
            const float w = __int_as_float(cw.y);
            const size_t o = (size_t)cw.x * (C_DIM / 2) + t;
            float2 v0 = __half22float2(__ldg(&T0[o]));
            float2 v1 = __half22float2(__ldg(&T1[o]));
            float2 v2 = __half22float2(__ldg(&T2[o]));
            p0.x += w * v0.x; p0.y += w * v0.y;
            p1.x += w * v1.x; p1.y += w * v1.y;
            p2.x += w * v2.x; p2.y += w * v2.y;
        }
        float w0 = wv2[comboOf[0][a]], w1 = wv2[comboOf[1][a]], w2 = wv2[comboOf[2][a]];
        agg[0].x += w0 * p0.x; agg[0].y += w0 * p0.y;
        agg[1].x += w1 * p1.x; agg[1].y += w1 * p1.y;
        agg[2].x += w2 * p2.x; agg[2].y += w2 * p2.y;
    }

    const size_t NC2 = (size_t)N_NODES * (C_DIM / 2);
    const size_t so = (size_t)i * (C_DIM / 2) + t;
    float2 ysum = {0.f, 0.f};
#pragma unroll
    for (int gc = 0; gc < 3; gc++) {
        float2 self = __half22float2(
            __ldg((const __half2*)g_emb2h + (size_t)(gc * 3) * NC2 + so));
        float2 bias = *(const float2*)&b2[gc * C_DIM + 2 * t];
        ysum.x += fmaxf(self.x + 1.01f * agg[gc].x + bias.x, 0.f);
        ysum.y += fmaxf(self.y + 1.01f * agg[gc].y + bias.y, 0.f);
    }
    const size_t oi = (size_t)i * C_DIM + 2 * t;
    *(float2*)&out[oi] = make_float2(fabsf(ysum.x * (1.f / 3.f)),
                                     fabsf(ysum.y * (1.f / 3.f)));
}

// ---------------------------------------------------------------------------
extern "C" void kernel_launch(void* const* d_in, const int* in_sizes, int n_in,
                              void* d_out, int out_size) {
    const float* x1 = (const float*)d_in[0];
    const float* x2 = (const float*)d_in[1];
    const float* x3 = (const float*)d_in[2];
    const int*   s0 = (const int*)d_in[3];
    const int*   d0 = (const int*)d_in[4];
    const float* v0 = (const float*)d_in[5];
    const int*   s1 = (const int*)d_in[6];
    const int*   d1 = (const int*)d_in[7];
    const float* v1 = (const float*)d_in[8];
    const int*   s2 = (const int*)d_in[9];
    const int*   d2 = (const int*)d_in[10];
    const float* v2 = (const float*)d_in[11];
    const float* W1  = (const float*)d_in[12];
    const float* wv1 = (const float*)d_in[13];
    const float* b1  = (const float*)d_in[14];
    const float* W2  = (const float*)d_in[15];
    const float* wv2 = (const float*)d_in[16];
    const float* b2  = (const float*)d_in[17];
    float* out = (float*)d_out;

    cudaFuncSetAttribute(gemm1_mma_kernel,
                         cudaFuncAttributeMaxDynamicSharedMemorySize, GSM_TOTAL);
    cudaFuncSetAttribute(gemm2_mma_kernel,
                         cudaFuncAttributeMaxDynamicSharedMemorySize, G2SM_TOTAL);

    // K0: zero cursors — separate launch, MUST complete before hist atomics
    csr_zero_kernel<<<(3 * N_NODES + 255) / 256, 256>>>();
    // K1: fused converts + histogram
    prep_kernel<<<NB_PREP, 256>>>(x1, x2, x3, W1, W2, s0, s1, s2);
    // K2: scan — own kernel (must precede the fill blocks in gemm1)
    csr_scan_kernel<<<3, 256>>>();
    // K3: gemm1 with fill blocks piggybacked at grid tail
    gemm1_mma_kernel<<<NB_GEMM1 + NB_FILL, 256, GSM_TOTAL>>>(
        s0, s1, s2, d0, d1, d2, v0, v1, v2);
    // K4-K6
    spmm1_kernel<<<N_NODES, 64>>>(wv1, b1);
    gemm2_mma_kernel<<<dim3(157, 9), 256, G2SM_TOTAL>>>();
    spmm2_kernel<<<N_NODES, 32>>>(wv2, b2, out);
}

// round 14
// speedup vs baseline: 1.1304x; 1.1304x over previous
#include <cuda_runtime.h>
#include <cuda_bf16.h>
#include <cuda_fp16.h>
#include <cstdint>

#define N_NODES 20000
#define F_DIM   512
#define H_DIM   128
#define C_DIM   64
#define N_EDGES 640000
#define PAD_ROWS 20096       // 157 * 128
#define RP_STRIDE 20004      // N_NODES+1 padded to 4-int alignment

// ---------------------------------------------------------------------------
// Scratch (static device globals; no runtime allocation allowed)
// ---------------------------------------------------------------------------
__device__ __half g_emb1h[9 * N_NODES * H_DIM];   // fp16 tables (combo); self = combo gc*3
__device__ __half g_emb2h[9 * N_NODES * C_DIM];

// fp16 GEMM operands (single-pass fp16 mma)
__device__ __half g_xh[3 * PAD_ROWS * F_DIM];     // [view][row][k]
__device__ __half g_wt[9 * H_DIM * F_DIM];        // [combo][n][k]
__device__ __half g_hh[3 * PAD_ROWS * H_DIM];     // [gc][row][k]
__device__ __half g_wt2[9 * C_DIM * H_DIM];       // [combo][n][k]

// CSR scratch
__device__ int  g_rowptr[3 * RP_STRIDE];
__device__ int  g_cursor[3 * N_NODES];
__device__ int2 g_edge[3 * N_EDGES];              // {col, w-as-int}

// combo -> which x / adjacency feeds it. combo = gc*3 + role.
__constant__ int c_perm[9] = {0,1,2, 1,0,2, 2,0,1};

// ---------------------------------------------------------------------------
// PTX helpers (base-target only: sm_80+ features)
// ---------------------------------------------------------------------------
__device__ __forceinline__ uint32_t smem_u32(const void* p) {
    uint32_t a;
    asm("{ .reg .u64 t; cvta.to.shared.u64 t, %1; cvt.u32.u64 %0, t; }"
        : "=r"(a) : "l"(p));
    return a;
}

__device__ __forceinline__ void cp_async16(uint32_t dst, const void* src) {
    asm volatile("cp.async.cg.shared.global [%0], [%1], 16;"
                 :: "r"(dst), "l"(src) : "memory");
}
#define CP_COMMIT() asm volatile("cp.async.commit_group;" ::: "memory")
#define CP_WAIT(n)  asm volatile("cp.async.wait_group %0;" :: "n"(n) : "memory")

__device__ __forceinline__ void ldsm_x4(uint32_t& r0, uint32_t& r1,
                                        uint32_t& r2, uint32_t& r3, uint32_t addr) {
    asm volatile("ldmatrix.sync.aligned.m8n8.x4.shared.b16 {%0,%1,%2,%3}, [%4];"
                 : "=r"(r0), "=r"(r1), "=r"(r2), "=r"(r3) : "r"(addr));
}

__device__ __forceinline__ void mma_f16(float* d, const uint32_t* a,
                                        const uint32_t* b) {
    asm volatile(
        "mma.sync.aligned.m16n8k16.row.col.f32.f16.f16.f32 "
        "{%0,%1,%2,%3}, {%4,%5,%6,%7}, {%8,%9}, {%0,%1,%2,%3};"
        : "+f"(d[0]), "+f"(d[1]), "+f"(d[2]), "+f"(d[3])
        : "r"(a[0]), "r"(a[1]), "r"(a[2]), "r"(a[3]), "r"(b[0]), "r"(b[1]));
}

__device__ __forceinline__ uint32_t h2u(__half2 h) {
    return *(uint32_t*)&h;
}

// ---------------------------------------------------------------------------
// K0: csr_zero — own kernel: all cursor zeroes visible before hist atomics.
// ---------------------------------------------------------------------------
__global__ void csr_zero_kernel() {
    int i = blockIdx.x * blockDim.x + threadIdx.x;
    if (i < 3 * N_NODES) g_cursor[i] = 0;
}

// ---------------------------------------------------------------------------
// K1: fused prep — cvt_x (x2 ILP) | cvt_w | cvt_w2 | csr_hist
// ---------------------------------------------------------------------------
#define NB_SPLITX 15000                  // 2 float4 per thread (strided)
#define SPLITX_STRIDE (NB_SPLITX * 256)
#define NB_SPLITW 2304
#define NB_SPLITW2 288
#define NB_HIST_PER 625
#define B_SPLITW  (NB_SPLITX)
#define B_SPLITW2 (B_SPLITW + NB_SPLITW)
#define B_HIST    (B_SPLITW2 + NB_SPLITW2)
#define NB_PREP   (B_HIST + 3 * NB_HIST_PER)

__global__ void __launch_bounds__(256)
prep_kernel(const float* __restrict__ x1, const float* __restrict__ x2,
            const float* __restrict__ x3, const float* __restrict__ W1,
            const float* __restrict__ W2,
            const int* __restrict__ s0, const int* __restrict__ s1,
            const int* __restrict__ s2) {
    const int bid = blockIdx.x;
    const int tid = threadIdx.x;

    if (bid < NB_SPLITX) {
#pragma unroll
        for (int r = 0; r < 2; r++) {
            int i = bid * 256 + tid + r * SPLITX_STRIDE;  // one float4
            const int per_view = N_NODES * (F_DIM / 4);
            const int view = i / per_view;
            const int rem  = i - view * per_view;
            const int row  = rem / (F_DIM / 4);
            const int kg   = rem - row * (F_DIM / 4);
            const float* X = (view == 0) ? x1 : (view == 1) ? x2 : x3;
            float4 f = ((const float4*)X)[rem];
            __half2 a = __float22half2_rn(make_float2(f.x, f.y));
            __half2 b = __float22half2_rn(make_float2(f.z, f.w));
            size_t off = ((size_t)view * PAD_ROWS + row) * F_DIM + kg * 4;
            *(uint2*)&g_xh[off] = make_uint2(h2u(a), h2u(b));
        }
    } else if (bid < B_SPLITW2) {
        int i = (bid - B_SPLITW) * 256 + tid;   // over 9*512*128, n fastest
        const int b = i / (F_DIM * H_DIM);
        const int rem = i - b * (F_DIM * H_DIM);
        const int k = rem / H_DIM;
        const int n = rem - k * H_DIM;
        g_wt[((size_t)b * H_DIM + n) * F_DIM + k] = __float2half_rn(W1[i]);
    } else if (bid < B_HIST) {
        int i = (bid - B_SPLITW2) * 256 + tid;  // over 9*128*64
        const int b = i / (H_DIM * C_DIM);
        const int rem = i - b * (H_DIM * C_DIM);
        const int k = rem / C_DIM;
        const int n = rem - k * C_DIM;
        g_wt2[((size_t)b * C_DIM + n) * H_DIM + k] = __float2half_rn(W2[i]);
    } else {
        const int rel = bid - B_HIST;
        const int a = rel / NB_HIST_PER;
        const int blk = rel - a * NB_HIST_PER;
        const int* __restrict__ s = (a == 0) ? s0 : (a == 1) ? s1 : s2;
        int* __restrict__ cur = g_cursor + a * N_NODES;
        const int base = blk * 1024 + tid;
#pragma unroll
        for (int k = 0; k < 4; k++)
            atomicAdd(&cur[__ldg(&s[base + k * 256])], 1);
    }
}

// ---------------------------------------------------------------------------
// K2: csr_scan — own kernel (3 blocks, 256 threads).
// ---------------------------------------------------------------------------
__global__ void __launch_bounds__(256) csr_scan_kernel() {
    const int a = blockIdx.x;
    __shared__ int s_warp[9];
    int* cnt = g_cursor + a * N_NODES;
    int* rp  = g_rowptr + a * RP_STRIDE;
    const int tid = threadIdx.x;
    const int lane = tid & 31;
    const int w = tid >> 5;
    int carry = 0;
    for (int base = 0; base < N_NODES; base += 1024) {
        const int idx = base + tid * 4;
        int v0 = 0, v1 = 0, v2 = 0, v3 = 0;
        if (idx + 3 < N_NODES) {
            int4 t = *(const int4*)&cnt[idx];
            v0 = t.x; v1 = t.y; v2 = t.z; v3 = t.w;
        } else {
            if (idx + 0 < N_NODES) v0 = cnt[idx + 0];
            if (idx + 1 < N_NODES) v1 = cnt[idx + 1];
            if (idx + 2 < N_NODES) v2 = cnt[idx + 2];
            if (idx + 3 < N_NODES) v3 = cnt[idx + 3];
        }
        const int tsum = v0 + v1 + v2 + v3;
        int sc = tsum;
#pragma unroll
        for (int o = 1; o < 32; o <<= 1) {
            int n = __shfl_up_sync(0xffffffff, sc, o);
            if (lane >= o) sc += n;
        }
        if (lane == 31) s_warp[w] = sc;
        __syncthreads();
        if (w == 0) {
            int x = (lane < 8) ? s_warp[lane] : 0;
#pragma unroll
            for (int o = 1; o < 8; o <<= 1) {
                int n = __shfl_up_sync(0xffffffff, x, o);
                if (lane >= o) x += n;
            }
            if (lane < 8) s_warp[lane] = x;
            if (lane == 7) s_warp[8] = x;
        }
        __syncthreads();
        const int warp_off = (w == 0) ? 0 : s_warp[w - 1];
        const int excl = carry + warp_off + (sc - tsum);
        const int p0 = excl, p1 = p0 + v0, p2 = p1 + v1, p3 = p2 + v2;
        if (idx + 3 < N_NODES) {
            *(int4*)&rp[idx]  = make_int4(p0, p1, p2, p3);
            *(int4*)&cnt[idx] = make_int4(p0, p1, p2, p3);
        } else {
            if (idx + 0 < N_NODES) { rp[idx + 0] = p0; cnt[idx + 0] = p0; }
            if (idx + 1 < N_NODES) { rp[idx + 1] = p1; cnt[idx + 1] = p1; }
            if (idx + 2 < N_NODES) { rp[idx + 2] = p2; cnt[idx + 2] = p2; }
            if (idx + 3 < N_NODES) { rp[idx + 3] = p3; cnt[idx + 3] = p3; }
        }
        carry += s_warp[8];
        __syncthreads();
    }
    if (tid == 0) rp[N_NODES] = carry;
}

// ---------------------------------------------------------------------------
// K3: GEMM1 (mma.sync fp16) with csr_fill piggybacked at the END of the grid.
// Single __syncthreads per K-iteration (measured neutral-positive in R13).
// ---------------------------------------------------------------------------
#define TILE_BYTES 16384                  // 128 rows x 128B
#define STAGE_BYTES (2 * TILE_BYTES)      // A + B
#define GSM_TOTAL (3 * STAGE_BYTES)       // 3 stages = 96KB
#define NB_GEMM1 (157 * 9)
#define NB_FILL (3 * NB_HIST_PER)

__global__ void __launch_bounds__(256, 2)
gemm1_mma_kernel(const int* __restrict__ s0, const int* __restrict__ s1,
                 const int* __restrict__ s2, const int* __restrict__ d0,
                 const int* __restrict__ d1, const int* __restrict__ d2,
                 const float* __restrict__ v0, const float* __restrict__ v1,
                 const float* __restrict__ v2) {
    if (blockIdx.x >= NB_GEMM1) {         // piggybacked fill blocks (grid tail)
        const int rel = blockIdx.x - NB_GEMM1;
        const int a = rel / NB_HIST_PER;
        const int blk = rel - a * NB_HIST_PER;
        const int*   __restrict__ s = (a == 0) ? s0 : (a == 1) ? s1 : s2;
        const int*   __restrict__ d = (a == 0) ? d0 : (a == 1) ? d1 : d2;
        const float* __restrict__ v = (a == 0) ? v0 : (a == 1) ? v1 : v2;
        int* __restrict__ cur = g_cursor + a * N_NODES;
        int2* __restrict__ eo = g_edge + (size_t)a * N_EDGES;
        const int base = blk * 1024 + threadIdx.x;
#pragma unroll
        for (int k = 0; k < 4; k++) {
            const int e = base + k * 256;
            const int ss = __ldg(&s[e]);
            const int dd = __ldg(&d[e]);
            const float vv = __ldg(&v[e]);
            int pos = atomicAdd(&cur[ss], 1);
            eo[pos] = make_int2(dd, __float_as_int(vv));
        }
        return;
    }
    extern __shared__ char smem[];
    const uint32_t sb = smem_u32(smem);
    const int tid = threadIdx.x;
    const int wid = tid >> 5;
    const int lane = tid & 31;
    const int gbid = blockIdx.x;
    const int tile = gbid % 157;
    const int b = gbid / 157;
    const int view = c_perm[b];
    const int rowBase = tile * 128;

    const int wm = wid >> 1;
    const int wn = wid & 1;

    const int arow_l = (lane & 15);
    const uint32_t akh = (uint32_t)(lane >> 4) * 16;
    const int brow_l = (lane & 7) + ((lane >> 4) << 3);
    const uint32_t bkh = (uint32_t)((lane >> 3) & 1) * 16;

    float cfrag[2][8][4];
#pragma unroll
    for (int mi = 0; mi < 2; mi++)
#pragma unroll
        for (int nj = 0; nj < 8; nj++)
#pragma unroll
            for (int q = 0; q < 4; q++) cfrag[mi][nj][q] = 0.f;

    const char* Abase = (const char*)(g_xh +
        ((size_t)view * PAD_ROWS + rowBase) * F_DIM);
    const char* Bbase = (const char*)(g_wt + (size_t)b * H_DIM * F_DIM);

    auto prefetch = [&](int c, int bufi) {
        const char* Asrc = Abase + c * 128;
        const char* Bsrc = Bbase + c * 128;
        const uint32_t Ab = sb + bufi * STAGE_BYTES;
        const uint32_t Bb = Ab + TILE_BYTES;
#pragma unroll
        for (int i = 0; i < 4; i++) {
            int idx = tid + i * 256;
            int row = idx >> 3;
            int ch  = idx & 7;
            uint32_t off = row * 128 + ch * 16;
            uint32_t sw = off ^ ((off >> 3) & 0x70);
            cp_async16(Ab + sw, Asrc + (size_t)row * (F_DIM * 2) + ch * 16);
            cp_async16(Bb + sw, Bsrc + (size_t)row * (F_DIM * 2) + ch * 16);
        }
        CP_COMMIT();
    };

    prefetch(0, 0);
    prefetch(1, 1);

    for (int it = 0; it < 8; it++) {
        const int bufi = it % 3;
        if (it < 7) { CP_WAIT(1); } else { CP_WAIT(0); }
        __syncthreads();
        if (it < 6) prefetch(it + 2, (it + 2) % 3);

        const uint32_t Ab = sb + bufi * STAGE_BYTES;
        const uint32_t Bb = Ab + TILE_BYTES;

#pragma unroll
        for (int k16 = 0; k16 < 4; k16++) {
            const uint32_t kb = k16 * 32;
            uint32_t afrag[2][4];
#pragma unroll
            for (int mi = 0; mi < 2; mi++) {
                const int row = wm * 32 + mi * 16 + arow_l;
                const uint32_t addr =
                    Ab + row * 128 + ((kb + akh) ^ (uint32_t)((row & 7) << 4));
                ldsm_x4(afrag[mi][0], afrag[mi][1], afrag[mi][2], afrag[mi][3], addr);
            }
            uint32_t bfrag[8][2];
#pragma unroll
            for (int bj = 0; bj < 4; bj++) {
                const int row = wn * 64 + bj * 16 + brow_l;
                const uint32_t addr =
                    Bb + row * 128 + ((kb + bkh) ^ (uint32_t)((row & 7) << 4));
                uint32_t r0, r1, r2, r3;
                ldsm_x4(r0, r1, r2, r3, addr);
                bfrag[bj * 2 + 0][0] = r0; bfrag[bj * 2 + 0][1] = r1;
                bfrag[bj * 2 + 1][0] = r2; bfrag[bj * 2 + 1][1] = r3;
            }
#pragma unroll
            for (int mi = 0; mi < 2; mi++)
#pragma unroll
                for (int nj = 0; nj < 8; nj++)
                    mma_f16(cfrag[mi][nj], afrag[mi], bfrag[nj]);
        }
    }

    // Epilogue: half table (self-term read from combo gc*3 in spmm1)
    __half* __restrict__ Couth = g_emb1h + (size_t)b * N_NODES * H_DIM;
    const int mrow0 = rowBase + wm * 32;
    const int ncol0 = wn * 64;
    const int lr = lane >> 2;
    const int lc = (lane & 3) * 2;
#pragma unroll
    for (int mi = 0; mi < 2; mi++) {
#pragma unroll
        for (int nj = 0; nj < 8; nj++) {
            const int r0 = mrow0 + mi * 16 + lr;
            const int cc = ncol0 + nj * 8 + lc;
            if (r0 < N_NODES)
                *(__half2*)&Couth[(size_t)r0 * H_DIM + cc] =
                    __float22half2_rn(make_float2(cfrag[mi][nj][0], cfrag[mi][nj][1]));
            if (r0 + 8 < N_NODES)
                *(__half2*)&Couth[(size_t)(r0 + 8) * H_DIM + cc] =
                    __float22half2_rn(make_float2(cfrag[mi][nj][2], cfrag[mi][nj][3]));
        }
    }
}

// ---------------------------------------------------------------------------
// GEMM2 (mma.sync fp16, single pass): emb2[b] = h[perm[b]] @ W2[b].
// 2 K-iterations, 2-stage cp.async. CTA tile 128x64.
// ---------------------------------------------------------------------------
#define T2_ABYTES 16384                   // 128 rows x 128B
#define T2_BBYTES 8192                    // 64 rows x 128B
#define T2_STAGE  (T2_ABYTES + T2_BBYTES)
#define G2SM_TOTAL (2 * T2_STAGE)         // 48KB

__global__ void __launch_bounds__(256, 2)
gemm2_mma_kernel() {
    extern __shared__ char smem[];
    const uint32_t sb = smem_u32(smem);
    const int tid = threadIdx.x;
    const int wid = tid >> 5;
    const int lane = tid & 31;
    const int tile = blockIdx.x;
    const int b = blockIdx.y;
    const int view = c_perm[b];
    const int rowBase = tile * 128;

    const int wm = wid >> 1;
    const int wn = wid & 1;

    const int arow_l = (lane & 15);
    const uint32_t akh = (uint32_t)(lane >> 4) * 16;
    const int brow_l = (lane & 7) + ((lane >> 4) << 3);
    const uint32_t bkh = (uint32_t)((lane >> 3) & 1) * 16;

    float cfrag[2][4][4];
#pragma unroll
    for (int mi = 0; mi < 2; mi++)
#pragma unroll
        for (int nj = 0; nj < 4; nj++)
#pragma unroll
            for (int q = 0; q < 4; q++) cfrag[mi][nj][q] = 0.f;

    const char* Abase = (const char*)(g_hh +
        ((size_t)view * PAD_ROWS + rowBase) * H_DIM);
    const char* Bbase = (const char*)(g_wt2 + (size_t)b * C_DIM * H_DIM);

    auto prefetch = [&](int c, int bufi) {
        const char* Asrc = Abase + c * 128;
        const char* Bsrc = Bbase + c * 128;
        const uint32_t Ab = sb + bufi * T2_STAGE;
        const uint32_t Bb = Ab + T2_ABYTES;
#pragma unroll
        for (int i = 0; i < 4; i++) {
            int idx = tid + i * 256;
            int row = idx >> 3;
            int ch  = idx & 7;
            uint32_t off = row * 128 + ch * 16;
            uint32_t sw = off ^ ((off >> 3) & 0x70);
            cp_async16(Ab + sw, Asrc + (size_t)row * (H_DIM * 2) + ch * 16);
        }
#pragma unroll
        for (int i = 0; i < 2; i++) {
            int idx = tid + i * 256;
            int row = idx >> 3;
            int ch  = idx & 7;
            uint32_t off = row * 128 + ch * 16;
            uint32_t sw = off ^ ((off >> 3) & 0x70);
            cp_async16(Bb + sw, Bsrc + (size_t)row * (H_DIM * 2) + ch * 16);
        }
        CP_COMMIT();
    };

    prefetch(0, 0);
    prefetch(1, 1);

#pragma unroll
    for (int it = 0; it < 2; it++) {
        if (it == 0) { CP_WAIT(1); } else { CP_WAIT(0); }
        __syncthreads();

        const uint32_t Ab = sb + it * T2_STAGE;
        const uint32_t Bb = Ab + T2_ABYTES;

#pragma unroll
        for (int k16 = 0; k16 < 4; k16++) {
            const uint32_t kb = k16 * 32;
            uint32_t afrag[2][4];
#pragma unroll
            for (int mi = 0; mi < 2; mi++) {
                const int row = wm * 32 + mi * 16 + arow_l;
                const uint32_t addr =
                    Ab + row * 128 + ((kb + akh) ^ (uint32_t)((row & 7) << 4));
                ldsm_x4(afrag[mi][0], afrag[mi][1], afrag[mi][2], afrag[mi][3], addr);
            }
            uint32_t bfrag[4][2];
#pragma unroll
            for (int bj = 0; bj < 2; bj++) {
                const int row = wn * 32 + bj * 16 + brow_l;
                const uint32_t addr =
                    Bb + row * 128 + ((kb + bkh) ^ (uint32_t)((row & 7) << 4));
                uint32_t r0, r1, r2, r3;
                ldsm_x4(r0, r1, r2, r3, addr);
                bfrag[bj * 2 + 0][0] = r0; bfrag[bj * 2 + 0][1] = r1;
                bfrag[bj * 2 + 1][0] = r2; bfrag[bj * 2 + 1][1] = r3;
            }
#pragma unroll
            for (int mi = 0; mi < 2; mi++)
#pragma unroll
                for (int nj = 0; nj < 4; nj++)
                    mma_f16(cfrag[mi][nj], afrag[mi], bfrag[nj]);
        }
        __syncthreads();
    }

    __half* __restrict__ Couth = g_emb2h + (size_t)b * N_NODES * C_DIM;
    const int mrow0 = rowBase + wm * 32;
    const int ncol0 = wn * 32;
    const int lr = lane >> 2;
    const int lc = (lane & 3) * 2;
#pragma unroll
    for (int mi = 0; mi < 2; mi++) {
#pragma unroll
        for (int nj = 0; nj < 4; nj++) {
            const int r0 = mrow0 + mi * 16 + lr;
            const int cc = ncol0 + nj * 8 + lc;
            if (r0 < N_NODES)
                *(__half2*)&Couth[(size_t)r0 * C_DIM + cc] =
                    __float22half2_rn(make_float2(cfrag[mi][nj][0], cfrag[mi][nj][1]));
            if (r0 + 8 < N_NODES)
                *(__half2*)&Couth[(size_t)(r0 + 8) * C_DIM + cc] =
                    __float22half2_rn(make_float2(cfrag[mi][nj][2], cfrag[mi][nj][3]));
        }
    }
}

// ---------------------------------------------------------------------------
// Fused SpMM layer 1: block per node, 64 threads (half2 column pair each).
// Simple 1-edge loop (R13 x2 unroll measured as a regression; reverted).
// ---------------------------------------------------------------------------
__global__ void __launch_bounds__(64) spmm1_kernel(const float* __restrict__ wv1,
                                                   const float* __restrict__ b1) {
    const int i = blockIdx.x;
    const int t = threadIdx.x;
    const int comboOf[3][3] = {{0, 1, 2}, {4, 3, 5}, {7, 8, 6}};

    float2 agg[3] = {{0.f, 0.f}, {0.f, 0.f}, {0.f, 0.f}};

#pragma unroll
    for (int a = 0; a < 3; a++) {
        const int start = g_rowptr[a * RP_STRIDE + i];
        const int end   = g_rowptr[a * RP_STRIDE + i + 1];
        const __half2* __restrict__ T0 =
            (const __half2*)g_emb1h + (size_t)comboOf[0][a] * N_NODES * (H_DIM / 2);
        const __half2* __restrict__ T1 =
            (const __half2*)g_emb1h + (size_t)comboOf[1][a] * N_NODES * (H_DIM / 2);
        const __half2* __restrict__ T2 =
            (const __half2*)g_emb1h + (size_t)comboOf[2][a] * N_NODES * (H_DIM / 2);
        const int2* __restrict__ ew = g_edge + (size_t)a * N_EDGES;

        float2 p0 = {0.f, 0.f}, p1 = {0.f, 0.f}, p2 = {0.f, 0.f};
        for (int e = start; e < end; e++) {
            const int2 cw = __ldg(&ew[e]);
            const float w = __int_as_float(cw.y);
            const size_t o = (size_t)cw.x * (H_DIM / 2) + t;
            float2 v0 = __half22float2(__ldg(&T0[o]));
            float2 v1 = __half22float2(__ldg(&T1[o]));
            float2 v2 = __half22float2(__ldg(&T2[o]));
            p0.x += w * v0.x; p0.y += w * v0.y;
            p1.x += w * v1.x; p1.y += w * v1.y;
            p2.x += w * v2.x; p2.y += w * v2.y;
        }
        float w0 = wv1[comboOf[0][a]], w1 = wv1[comboOf[1][a]], w2 = wv1[comboOf[2][a]];
        agg[0].x += w0 * p0.x; agg[0].y += w0 * p0.y;
        agg[1].x += w1 * p1.x; agg[1].y += w1 * p1.y;
        agg[2].x += w2 * p2.x; agg[2].y += w2 * p2.y;
    }

    const size_t NH2 = (size_t)N_NODES * (H_DIM / 2);
    const size_t PH = (size_t)PAD_ROWS * H_DIM;
    const size_t so = (size_t)i * (H_DIM / 2) + t;
#pragma unroll
    for (int gc = 0; gc < 3; gc++) {
        float2 self = __half22float2(
            __ldg((const __half2*)g_emb1h + (size_t)(gc * 3) * NH2 + so));
        float2 bias = *(const float2*)&b1[gc * H_DIM + 2 * t];
        float hx = fmaxf(self.x + 1.01f * agg[gc].x + bias.x, 0.f);
        float hy = fmaxf(self.y + 1.01f * agg[gc].y + bias.y, 0.f);
        const size_t base = (size_t)gc * PH + (size_t)i * H_DIM + 2 * t;
        *(uint32_t*)&g_hh[base] = h2u(__float22half2_rn(make_float2(hx, hy)));
    }
}

// ---------------------------------------------------------------------------
// Fused SpMM layer 2 + final: block per node, 32 threads. Simple 1-edge loop.
// ---------------------------------------------------------------------------
__global__ void __launch_bounds__(32) spmm2_kernel(const float* __restrict__ wv2,
                                                   const float* __restrict__ b2,
                                                   float* __restrict__ out) {
    const int i = blockIdx.x;
    const int t = threadIdx.x;
    const int comboOf[3][3] = {{0, 1, 2}, {4, 3, 5}, {7, 8, 6}};

    float2 agg[3] = {{0.f, 0.f}, {0.f, 0.f}, {0.f, 0.f}};

#pragma unroll
    for (int a = 0; a < 3; a++) {
        const int start = g_rowptr[a * RP_STRIDE + i];
        const int end   = g_rowptr[a * RP_STRIDE + i + 1];
        const __half2* __restrict__ T0 =
            (const __half2*)g_emb2h + (size_t)comboOf[0][a] * N_NODES * (C_DIM / 2);
        const __half2* __restrict__ T1 =
            (const __half2*)g_emb2h + (size_t)comboOf[1][a] * N_NODES * (C_DIM / 2);
        const __half2* __restrict__ T2 =
            (const __half2*)g_emb2h + (size_t)comboOf[2][a] * N_NODES * (C_DIM / 2);
        const int2* __restrict__ ew = g_edge + (size_t)a * N_EDGES;

        float2 p0 = {0.f, 0.f}, p1 = {0.f, 0.f}, p2 = {0.f, 0.f};
        for (int e = start; e < end; e++) {
            const int2 cw = __ldg(&ew[e]);
            const float w = __int_as_float(cw.y);
            const size_t o = (size_t)cw.x * (C_DIM / 2) + t;
            float2 v0 = __half22float2(__ldg(&T0[o]));
            float2 v1 = __half22float2(__ldg(&T1[o]));
            float2 v2 = __half22float2(__ldg(&T2[o]));
            p0.x += w * v0.x; p0.y += w * v0.y;
            p1.x += w * v1.x; p1.y += w * v1.y;
            p2.x += w * v2.x; p2.y += w * v2.y;
        }
        float w0 = wv2[comboOf[0][a]], w1 = wv2[comboOf[1][a]], w2 = wv2[comboOf[2][a]];
        agg[0].x += w0 * p0.x; agg[0].y += w0 * p0.y;
        agg[1].x += w1 * p1.x; agg[1].y += w1 * p1.y;
        agg[2].x += w2 * p2.x; agg[2].y += w2 * p2.y;
    }

    const size_t NC2 = (size_t)N_NODES * (C_DIM / 2);
    const size_t so = (size_t)i * (C_DIM / 2) + t;
    float2 ysum = {0.f, 0.f};
#pragma unroll
    for (int gc = 0; gc < 3; gc++) {
        float2 self = __half22float2(
            __ldg((const __half2*)g_emb2h + (size_t)(gc * 3) * NC2 + so));
        float2 bias = *(const float2*)&b2[gc * C_DIM + 2 * t];
        ysum.x += fmaxf(self.x + 1.01f * agg[gc].x + bias.x, 0.f);
        ysum.y += fmaxf(self.y + 1.01f * agg[gc].y + bias.y, 0.f);
    }
    const size_t oi = (size_t)i * C_DIM + 2 * t;
    *(float2*)&out[oi] = make_float2(fabsf(ysum.x * (1.f / 3.f)),
                                     fabsf(ysum.y * (1.f / 3.f)));
}

// ---------------------------------------------------------------------------
extern "C" void kernel_launch(void* const* d_in, const int* in_sizes, int n_in,
                              void* d_out, int out_size) {
    const float* x1 = (const float*)d_in[0];
    const float* x2 = (const float*)d_in[1];
    const float* x3 = (const float*)d_in[2];
    const int*   s0 = (const int*)d_in[3];
    const int*   d0 = (const int*)d_in[4];
    const float* v0 = (const float*)d_in[5];
    const int*   s1 = (const int*)d_in[6];
    const int*   d1 = (const int*)d_in[7];
    const float* v1 = (const float*)d_in[8];
    const int*   s2 = (const int*)d_in[9];
    const int*   d2 = (const int*)d_in[10];
    const float* v2 = (const float*)d_in[11];
    const float* W1  = (const float*)d_in[12];
    const float* wv1 = (const float*)d_in[13];
    const float* b1  = (const float*)d_in[14];
    const float* W2  = (const float*)d_in[15];
    const float* wv2 = (const float*)d_in[16];
    const float* b2  = (const float*)d_in[17];
    float* out = (float*)d_out;

    cudaFuncSetAttribute(gemm1_mma_kernel,
                         cudaFuncAttributeMaxDynamicSharedMemorySize, GSM_TOTAL);
    cudaFuncSetAttribute(gemm2_mma_kernel,
                         cudaFuncAttributeMaxDynamicSharedMemorySize, G2SM_TOTAL);

    // K0: zero cursors — separate launch, MUST complete before hist atomics
    csr_zero_kernel<<<(3 * N_NODES + 255) / 256, 256>>>();
    // K1: fused converts + histogram
    prep_kernel<<<NB_PREP, 256>>>(x1, x2, x3, W1, W2, s0, s1, s2);
    // K2: scan — own kernel (must precede the fill blocks in gemm1)
    csr_scan_kernel<<<3, 256>>>();
    // K3: gemm1 with fill blocks piggybacked at grid tail
    gemm1_mma_kernel<<<NB_GEMM1 + NB_FILL, 256, GSM_TOTAL>>>(
        s0, s1, s2, d0, d1, d2, v0, v1, v2);
    // K4-K6
    spmm1_kernel<<<N_NODES, 64>>>(wv1, b1);
    gemm2_mma_kernel<<<dim3(157, 9), 256, G2SM_TOTAL>>>();
    spmm2_kernel<<<N_NODES, 32>>>(wv2, b2, out);
}